// round 16
// baseline (speedup 1.0000x reference)
#include <cuda_runtime.h>
#include <cuda_bf16.h>
#include <cstdint>
#include <cstddef>

#define Hdim 1024
#define Edim 18432
#define Vdim 32000
#define Tlen 15

// fcr grid layout: comb3 | hh(3x512) | fcb8 | refine
#define NC3 512
#define NHH 1536
#define NFC 1000
#define NRF 125
#define GRID_FCR (NC3 + NHH + NFC + NRF)

struct State {
    float feat[Hdim];
    float h[Hdim], c[Hdim];
    float tmph[Hdim], tmpc[Hdim];
    float h1[Hdim], c1[Hdim];
    float h2[2][Hdim], c2[2][Hdim];
    float h3[2][Hdim], c3[2][Hdim];
    float word[Hdim];
    float hi[Vdim];
    unsigned long long lomax, exmax;
    unsigned ticket1, ticket3, tickF, tickC;
};
__device__ State g_s;
__device__ unsigned g_fcw8[(size_t)Vdim * (Hdim / 4)];  // int8-packed fc_w (32.8 MB)
__device__ float g_scale[Vdim];
__device__ float g_sumw[Vdim];
__device__ float g_hhp[3][4 * Hdim];   // hh partials (+bhh) for cells 1..3 of next step

// ---------- helpers ----------
__device__ __forceinline__ float sigf(float x) { return 1.0f / (1.0f + expf(-x)); }

__device__ __forceinline__ float warp_sum(float s) {
#pragma unroll
    for (int o = 16; o; o >>= 1) s += __shfl_xor_sync(0xffffffffu, s, o);
    return s;
}
__device__ __forceinline__ int warp_isum(int s) {
#pragma unroll
    for (int o = 16; o; o >>= 1) s += __shfl_xor_sync(0xffffffffu, s, o);
    return s;
}
__device__ __forceinline__ float warp_max(float s) {
#pragma unroll
    for (int o = 16; o; o >>= 1) s = fmaxf(s, __shfl_xor_sync(0xffffffffu, s, o));
    return s;
}

__device__ __forceinline__ float block_sum(float s) {
    __shared__ float sm[8];
    __shared__ float outv;
    int w = threadIdx.x >> 5, lane = threadIdx.x & 31;
    s = warp_sum(s);
    if (lane == 0) sm[w] = s;
    __syncthreads();
    if (w == 0) {
        float r = (lane < 8) ? sm[lane] : 0.0f;
        r = warp_sum(r);
        if (lane == 0) outv = r;
    }
    __syncthreads();
    float res = outv;
    __syncthreads();
    return res;
}

__device__ __forceinline__ unsigned long long packkey(float v, unsigned idx) {
    unsigned u = __float_as_uint(v);
    u = (u & 0x80000000u) ? ~u : (u | 0x80000000u);
    return ((unsigned long long)u << 32) | (unsigned long long)(0xFFFFFFFFu - idx);
}
__device__ __forceinline__ float key_val(unsigned long long k) {
    unsigned u = (unsigned)(k >> 32);
    u = (u & 0x80000000u) ? (u ^ 0x80000000u) : ~u;
    return __uint_as_float(u);
}
__device__ __forceinline__ int key_idx(unsigned long long k) {
    return (int)(0xFFFFFFFFu - (unsigned)(k & 0xFFFFFFFFull));
}

__device__ __forceinline__ int clamp127(int q) {
    return q < -127 ? -127 : (q > 127 ? 127 : q);
}
__device__ __forceinline__ unsigned pack4(float4 f, float inv) {
    int a = clamp127(__float2int_rn(f.x * inv));
    int b = clamp127(__float2int_rn(f.y * inv));
    int c = clamp127(__float2int_rn(f.z * inv));
    int d = clamp127(__float2int_rn(f.w * inv));
    return (a & 0xFF) | ((b & 0xFF) << 8) | ((c & 0xFF) << 16) | ((d & 0xFF) << 24);
}

__device__ __forceinline__ void spin_on(unsigned* c, unsigned target) {
    if (target == 0u) return;
    if (threadIdx.x == 0) {
        volatile unsigned* vc = (volatile unsigned*)c;
        while (*vc < target) __nanosleep(64);
    }
    __syncthreads();
}

// ---------- LayerNorm by one 256-thread block ----------
__device__ void ln256(const float* __restrict__ x, const float* __restrict__ g,
                      const float* __restrict__ b, const float* __restrict__ base,
                      float* __restrict__ o) {
    float xv[4];
    float s = 0.f;
#pragma unroll
    for (int k = 0; k < 4; k++) { xv[k] = x[threadIdx.x + 256 * k]; s += xv[k]; }
    float m = block_sum(s) * (1.f / Hdim);
    float q = 0.f;
#pragma unroll
    for (int k = 0; k < 4; k++) { float d = xv[k] - m; q += d * d; }
    float v = block_sum(q) * (1.f / Hdim);
    float inv = rsqrtf(v + 1e-5f);
#pragma unroll
    for (int k = 0; k < 4; k++) {
        int i = threadIdx.x + 256 * k;
        float r = (xv[k] - m) * inv * g[i] + b[i];
        if (base) r += base[i];
        o[i] = r;
    }
}

// ---------- combine row pair (R12 shape): ih GEMV + hh partial + pointwise ----------
// FENCE: writers issue __threadfence so a following counter-add publishes results.
template <bool FENCE>
__device__ __forceinline__ void comb_row(
    int b, const float* __restrict__ x, const float* __restrict__ cin, int set,
    const float* __restrict__ wih, const float* __restrict__ bih,
    float* __restrict__ hout, float* __restrict__ cout) {
    __shared__ float red[8];
    int tid = threadIdx.x;
    int w = tid >> 5, lane = tid & 31;
    int g = w & 3, rl = w >> 2;
    int j = b * 2 + rl;
    int row = g * Hdim + j;
    const float4* Wr = (const float4*)(wih + (size_t)row * Hdim);
    const float4* v4 = (const float4*)x;
    float s = 0.f;
#pragma unroll
    for (int i = 0; i < 8; i++) {
        float4 a = Wr[lane + 32 * i];
        float4 vb = __ldcg(v4 + lane + 32 * i);
        s += a.x * vb.x + a.y * vb.y + a.z * vb.z + a.w * vb.w;
    }
    s = warp_sum(s);
    if (lane == 0) red[w] = s + bih[row] + g_hhp[set][row];
    __syncthreads();
    if (tid == 0 || tid == 128) {
        int rr = tid >> 7;
        int jj = b * 2 + rr;
        float gi = red[rr * 4 + 0], gf = red[rr * 4 + 1];
        float gg = red[rr * 4 + 2], go = red[rr * 4 + 3];
        float cn = sigf(gf) * __ldcg(&cin[jj]) + sigf(gi) * tanhf(gg);
        cout[jj] = cn;
        hout[jj] = sigf(go) * tanhf(cn);
        if (FENCE) __threadfence();
    }
    if (FENCE) __syncthreads();
}

// ---------- hh-half GEMV body ----------
__device__ __forceinline__ void hh_body(int set, int b, const float* __restrict__ hin,
                                        const float* __restrict__ W,
                                        const float* __restrict__ bb, bool viaL2) {
    int w = threadIdx.x >> 5, lane = threadIdx.x & 31;
    int g = w & 3, rl = w >> 2;
    int row = g * Hdim + b * 2 + rl;
    const float4* Wr = (const float4*)(W + (size_t)row * Hdim);
    const float4* v4 = (const float4*)hin;
    float s = 0.f;
#pragma unroll
    for (int i = 0; i < 8; i++) {
        float4 a = Wr[lane + 32 * i];
        float4 vb = viaL2 ? __ldcg(v4 + lane + 32 * i) : v4[lane + 32 * i];
        s += a.x * vb.x + a.y * vb.y + a.z * vb.z + a.w * vb.w;
    }
    s = warp_sum(s);
    if (lane == 0) g_hhp[set][row] = s + bb[row];
}

// ---------- prologue: fc1 rows (blocks < Hdim) + int8 quantize fc_w (rest) ----------
__global__ void __launch_bounds__(256) k_pro1(
    const float* __restrict__ feats, const float* __restrict__ w,
    const float* __restrict__ bias, const float* __restrict__ fcw32) {
    int wid = threadIdx.x >> 5, lane = threadIdx.x & 31;
    if (blockIdx.x < Hdim) {
        int j = blockIdx.x;
        const float4* Wr = (const float4*)(w + (size_t)j * Edim);
        const float4* X  = (const float4*)feats;
        float s = 0.f;
        for (int i = threadIdx.x; i < Edim / 4; i += 256) {
            float4 a = __ldcs(&Wr[i]), v = X[i];
            s += a.x * v.x + a.y * v.y + a.z * v.z + a.w * v.w;
        }
        s = block_sum(s);
        if (threadIdx.x == 0) g_s.feat[j] = fmaxf(s + bias[j], 0.f);
    } else {
        int r = (blockIdx.x - Hdim) * 8 + wid;
        const float4* Wr = (const float4*)(fcw32 + (size_t)r * Hdim);
        float4 v[8];
        float ma = 0.f, sa = 0.f;
#pragma unroll
        for (int k = 0; k < 8; k++) {
            v[k] = __ldcs(&Wr[lane + 32 * k]);
            ma = fmaxf(ma, fmaxf(fmaxf(fabsf(v[k].x), fabsf(v[k].y)),
                                 fmaxf(fabsf(v[k].z), fabsf(v[k].w))));
            sa += fabsf(v[k].x) + fabsf(v[k].y) + fabsf(v[k].z) + fabsf(v[k].w);
        }
        ma = warp_max(ma);
        sa = warp_sum(sa);
        float mg = fmaxf(ma, 1e-30f);
        float s = mg * (1.f / 127.f);
        float inv = 127.f / mg;
        unsigned* W8 = g_fcw8 + (size_t)r * (Hdim / 4);
#pragma unroll
        for (int k = 0; k < 8; k++) W8[lane + 32 * k] = pack4(v[k], inv);
        if (lane == 0) { g_scale[r] = s; g_sumw[r] = sa; }
    }
}

// ---------- init h/c GEMVs + (last block) prologue LayerNorms ----------
__global__ void __launch_bounds__(256) k_init2(
    const float* __restrict__ wh, const float* __restrict__ bh,
    const float* __restrict__ wc, const float* __restrict__ bc,
    const float* __restrict__ lnhg, const float* __restrict__ lnhb,
    const float* __restrict__ lncg, const float* __restrict__ lncb) {
    int j = blockIdx.x;
    bool ish = j < Hdim;
    int r = ish ? j : j - Hdim;
    const float4* Wr = (const float4*)((ish ? wh : wc) + (size_t)r * Hdim);
    const float4* X  = (const float4*)g_s.feat;
    float4 a = __ldcs(&Wr[threadIdx.x]), v = X[threadIdx.x];
    float s = a.x * v.x + a.y * v.y + a.z * v.z + a.w * v.w;
    s = block_sum(s);
    __shared__ bool lastb;
    if (threadIdx.x == 0) {
        float val = fmaxf(s + (ish ? bh[r] : bc[r]), 0.f);
        if (ish) g_s.tmph[r] = val; else g_s.tmpc[r] = val;
        __threadfence();
        lastb = (atomicAdd(&g_s.ticket1, 1u) == 2u * Hdim - 1u);
    }
    __syncthreads();
    if (!lastb) return;
    ln256(g_s.tmph, lnhg, lnhb, nullptr, g_s.h);
    ln256(g_s.tmpc, lncg, lncb, nullptr, g_s.c);
    if (threadIdx.x == 0) g_s.ticket1 = 0;
}

// ---------- full LSTM cell (step 0 only; R7/R12-proven) ----------
template <bool FUSELN>
__global__ void __launch_bounds__(256) k_cell(
    const float* __restrict__ x, const float* __restrict__ hin, const float* __restrict__ cin,
    const float* __restrict__ wih, const float* __restrict__ whh,
    const float* __restrict__ bih, const float* __restrict__ bhh,
    float* __restrict__ hout, float* __restrict__ cout,
    const float* __restrict__ lnhg, const float* __restrict__ lnhb,
    const float* __restrict__ lncg, const float* __restrict__ lncb) {
    if (FUSELN && blockIdx.x >= Hdim) {
        bool ish = (blockIdx.x == Hdim);
        ln256(ish ? g_s.h1 : g_s.c1,
              ish ? lnhg : lncg, ish ? lnhb : lncb,
              ish ? g_s.h : g_s.c,
              ish ? g_s.tmph : g_s.tmpc);
        return;
    }
    int j = blockIdx.x;
    int w = threadIdx.x >> 5, lane = threadIdx.x & 31;
    const float* Wm  = (w < 4) ? wih : whh;
    const float* vec = (w < 4) ? x : hin;
    int row = j + (w & 3) * Hdim;
    const float4* Wr = (const float4*)(Wm + (size_t)row * Hdim);
    const float4* v4 = (const float4*)vec;
    float s = 0.f;
#pragma unroll
    for (int i = 0; i < 8; i++) {
        float4 a = Wr[lane + 32 * i];
        float4 b = v4[lane + 32 * i];
        s += a.x * b.x + a.y * b.y + a.z * b.z + a.w * b.w;
    }
    s = warp_sum(s);
    __shared__ float red[8];
    if (lane == 0) red[w] = s;
    __syncthreads();
    if (threadIdx.x == 0) {
        float gi = red[0] + red[4] + bih[j]            + bhh[j];
        float gf = red[1] + red[5] + bih[j + Hdim]     + bhh[j + Hdim];
        float gg = red[2] + red[6] + bih[j + 2 * Hdim] + bhh[j + 2 * Hdim];
        float go = red[3] + red[7] + bih[j + 3 * Hdim] + bhh[j + 3 * Hdim];
        float cn = sigf(gf) * cin[j] + sigf(gi) * tanhf(gg);
        cout[j] = cn;
        hout[j] = sigf(go) * tanhf(cn);
    }
}

// ---------- combine kernel (steps 1..14, cells 1 and 2; R12 shape) ----------
template <bool FUSELN>
__global__ void __launch_bounds__(256) k_comb(
    const float* __restrict__ x, const float* __restrict__ cin, int set,
    const float* __restrict__ wih, const float* __restrict__ bih,
    float* __restrict__ hout, float* __restrict__ cout,
    const float* __restrict__ lnhg, const float* __restrict__ lnhb,
    const float* __restrict__ lncg, const float* __restrict__ lncb) {
    if (FUSELN && blockIdx.x >= 512) {
        bool ish = (blockIdx.x == 512);
        ln256(ish ? g_s.h1 : g_s.c1,
              ish ? lnhg : lncg, ish ? lnhb : lncb,
              ish ? g_s.h : g_s.c,
              ish ? g_s.tmph : g_s.tmpc);
        return;
    }
    comb_row<false>(blockIdx.x, x, cin, set, wih, bih, hout, cout);
}

// ---------- mega-kernel: comb3 + hh(next step) + fcb8 + refine ----------
// bid order: comb3 [0,NC3) -> hh [NC3,NC3+NHH) -> fcb8 -> refine.
// hh set2 and fcb8 spin on comb3 counter (target 0 when do_c3 == 0).
__global__ void __launch_bounds__(256) k_fcr(
    float* __restrict__ h3buf, float* __restrict__ c3buf,
    const float* __restrict__ h2cur, const float* __restrict__ c3prev,
    const float* __restrict__ w_ih2, const float* __restrict__ b_ih2,
    const float* __restrict__ w_hh1, const float* __restrict__ w_hh2,
    const float* __restrict__ b_hh1, const float* __restrict__ b_hh2,
    const float* __restrict__ fcb, const float* __restrict__ fcw32,
    const float* __restrict__ embed, const float* __restrict__ tot,
    float* __restrict__ out, int t, int do_hh, int do_c3) {
    int bid = blockIdx.x;
    int tid = threadIdx.x, wid = tid >> 5, lane = tid & 31;
    const float4* X = (const float4*)h3buf;
    unsigned c3t = do_c3 ? (unsigned)NC3 : 0u;

    if (bid < NC3) {   // ---- comb3: cell-3 combine, publishes h3/c3 ----
        if (do_c3) {
            comb_row<true>(bid, h2cur, c3prev, 2, w_ih2, b_ih2, h3buf, c3buf);
            if (tid == 0) atomicAdd(&g_s.tickC, 1u);
        }
        return;
    }

    if (bid < NC3 + NHH) {   // ---- hh GEMVs for the next step ----
        if (do_hh) {
            int local = bid - NC3;
            int set = local >> 9, b = local & 511;
            if (set == 0)      hh_body(0, b, g_s.tmph, w_hh1, b_hh1, false);
            else if (set == 1) hh_body(1, b, h2cur, w_hh2, b_hh2, false);
            else {             // set 2 needs h3 (produced in-launch)
                spin_on(&g_s.tickC, c3t);
                hh_body(2, b, h3buf, w_hh2, b_hh2, true);
            }
        }
        return;
    }

    if (bid < NC3 + NHH + NFC) {   // ---- fcb8 ----
        spin_on(&g_s.tickC, c3t);
        float4 xv[8];
        float ma = 0.f, sa = 0.f;
#pragma unroll
        for (int k = 0; k < 8; k++) {
            xv[k] = __ldcg(&X[lane + 32 * k]);
            ma = fmaxf(ma, fmaxf(fmaxf(fabsf(xv[k].x), fabsf(xv[k].y)),
                                 fmaxf(fabsf(xv[k].z), fabsf(xv[k].w))));
            sa += fabsf(xv[k].x) + fabsf(xv[k].y) + fabsf(xv[k].z) + fabsf(xv[k].w);
        }
        ma = warp_max(ma);
        float sumAbsX = warp_sum(sa);
        float mg = fmaxf(ma, 1e-30f);
        float sx = mg * (1.f / 127.f);
        float invx = 127.f / mg;
        unsigned qx[8];
#pragma unroll
        for (int k = 0; k < 8; k++) qx[k] = pack4(xv[k], invx);
        unsigned long long wbest = 0ull;
        int r0 = ((bid - NC3 - NHH) * 8 + wid) * 4;
#pragma unroll
        for (int rr = 0; rr < 4; rr++) {
            int r = r0 + rr;
            const unsigned* W8 = g_fcw8 + (size_t)r * (Hdim / 4);
            int acc = 0;
#pragma unroll
            for (int k = 0; k < 8; k++)
                acc = __dp4a((int)W8[lane + 32 * k], (int)qx[k], acc);
            acc = warp_isum(acc);
            if (lane == 0) {
                float sr = g_scale[r];
                float v = sr * sx * (float)acc + fcb[r];
                float err = (0.5f * sx * g_sumw[r] + 0.5f * sr * (sumAbsX + 512.f * sx)) * 1.1f
                            + 1e-7f;
                g_s.hi[r] = v + err;
                unsigned long long key = packkey(v - err, (unsigned)r);
                if (key > wbest) wbest = key;
            }
        }
        __shared__ unsigned long long sb[8];
        if (lane == 0) sb[wid] = wbest;
        __syncthreads();
        if (tid == 0) {
            unsigned long long m = sb[0];
#pragma unroll
            for (int k = 1; k < 8; k++) if (sb[k] > m) m = sb[k];
            atomicMax(&g_s.lomax, m);
            __threadfence();
            atomicAdd(&g_s.tickF, 1u);
        }
        return;
    }

    // ---- refine (NRF blocks; spin until all fcb8 blocks done) ----
    if (tid == 0) {
        volatile unsigned* vc = &g_s.tickF;
        while (*vc < (unsigned)NFC) __nanosleep(64);
    }
    __syncthreads();
    int rb = bid - (NC3 + NHH + NFC);
    __shared__ int cand[256];
    __shared__ int cnt;
    __shared__ unsigned long long swr[8];
    __shared__ bool lastb;
    __shared__ int s_idx;
    __shared__ float s_tok;
    if (tid == 0) cnt = 0;
    __syncthreads();
    float lo = key_val(g_s.lomax);
    int r = rb * 256 + tid;
    if (__ldcg(&g_s.hi[r]) >= lo) cand[atomicAdd(&cnt, 1)] = r;
    __syncthreads();
    float4 x4c[8];
#pragma unroll
    for (int k = 0; k < 8; k++) x4c[k] = __ldcg(&X[lane + 32 * k]);
    unsigned long long rbest = 0ull;
    int n = cnt;
    for (int ci = wid; ci < n; ci += 8) {
        int row = cand[ci];
        const float4* Wr = (const float4*)(fcw32 + (size_t)row * Hdim);
        float d = 0.f;
#pragma unroll
        for (int k = 0; k < 8; k++) {
            float4 a = Wr[lane + 32 * k];
            d += a.x * x4c[k].x + a.y * x4c[k].y + a.z * x4c[k].z + a.w * x4c[k].w;
        }
        d = warp_sum(d);
        if (lane == 0) {
            unsigned long long key = packkey(d + fcb[row], (unsigned)row);
            if (key > rbest) rbest = key;
        }
    }
    if (lane == 0) swr[wid] = rbest;
    __syncthreads();
    if (tid == 0) {
        unsigned long long m = swr[0];
#pragma unroll
        for (int k = 1; k < 8; k++) if (swr[k] > m) m = swr[k];
        if (m) atomicMax(&g_s.exmax, m);
        __threadfence();
        lastb = (atomicAdd(&g_s.ticket3, 1u) == NRF - 1u);
    }
    __syncthreads();
    if (!lastb) return;

    if (tid == 0) {
        unsigned long long m = atomicAdd(&g_s.exmax, 0ull);
        s_idx = key_idx(m);
        s_tok = tot[s_idx];
        g_s.lomax = 0ull;
        g_s.exmax = 0ull;
        g_s.ticket3 = 0u;
        g_s.tickF = 0u;
        g_s.tickC = 0u;
    }
    __syncthreads();
    int idx = s_idx;
    ((float4*)g_s.word)[tid] = ((const float4*)(embed + (size_t)idx * Hdim))[tid];
    out[tid * Tlen + t] = s_tok;   // batch == 256 == blockDim
}

extern "C" void kernel_launch(void* const* d_in, const int* in_sizes, int n_in,
                              void* d_out, int out_size) {
    const float* features  = (const float*)d_in[0];
    const float* fc1_w     = (const float*)d_in[1];
    const float* fc1_b     = (const float*)d_in[2];
    const float* init_h_w  = (const float*)d_in[3];
    const float* init_h_b  = (const float*)d_in[4];
    const float* init_c_w  = (const float*)d_in[5];
    const float* init_c_b  = (const float*)d_in[6];
    const float* ln_h_g    = (const float*)d_in[7];
    const float* ln_h_b    = (const float*)d_in[8];
    const float* ln_c_g    = (const float*)d_in[9];
    const float* ln_c_b    = (const float*)d_in[10];
    const float* w_ih1     = (const float*)d_in[11];
    const float* w_hh1     = (const float*)d_in[12];
    const float* b_ih1     = (const float*)d_in[13];
    const float* b_hh1     = (const float*)d_in[14];
    const float* w_ih2     = (const float*)d_in[15];
    const float* w_hh2     = (const float*)d_in[16];
    const float* b_ih2     = (const float*)d_in[17];
    const float* b_hh2     = (const float*)d_in[18];
    const float* fc_w      = (const float*)d_in[19];
    const float* fc_b      = (const float*)d_in[20];
    const float* embed_w   = (const float*)d_in[21];
    const float* totoken_w = (const float*)d_in[22];
    float* out = (float*)d_out;

    State* S = nullptr;
    cudaGetSymbolAddress((void**)&S, g_s);
    const float* FN = nullptr;

    // prologue
    k_pro1<<<Hdim + Vdim / 8, 256>>>(features, fc1_w, fc1_b, fc_w);
    k_init2<<<2 * Hdim, 256>>>(init_h_w, init_h_b, init_c_w, init_c_b,
                               ln_h_g, ln_h_b, ln_c_g, ln_c_b);

    // ---- step 0: full cells; fcr with comb3 disabled (h3 already computed) ----
    k_cell<false><<<Hdim, 256>>>(S->feat, S->h, S->c,
        w_ih1, w_hh1, b_ih1, b_hh1, S->h1, S->c1, FN, FN, FN, FN);
    k_cell<true><<<Hdim + 2, 256>>>(S->h1, S->h, S->c,
        w_ih2, w_hh2, b_ih2, b_hh2, S->h2[0], S->c2[0],
        ln_h_g, ln_h_b, ln_c_g, ln_c_b);
    k_cell<false><<<Hdim, 256>>>(S->h2[0], S->h, S->c,
        w_ih2, w_hh2, b_ih2, b_hh2, S->h3[0], S->c3[0], FN, FN, FN, FN);
    k_fcr<<<GRID_FCR, 256>>>(S->h3[0], S->c3[0], S->h2[0], S->c,
        w_ih2, b_ih2, w_hh1, w_hh2, b_hh1, b_hh2,
        fc_b, fc_w, embed_w, totoken_w, out, 0, 1, 0);

    // ---- steps 1..14: comb1, comb2+LN, then mega (comb3+hh+fcb8+refine) ----
    for (int t = 1; t < Tlen; t++) {
        int q = t & 1, p = q ^ 1;
        k_comb<false><<<512, 256>>>(S->word, S->tmpc, 0, w_ih1, b_ih1,
                                    S->h1, S->c1, FN, FN, FN, FN);
        k_comb<true><<<514, 256>>>(S->h1, S->c2[p], 1, w_ih2, b_ih2,
                                   S->h2[q], S->c2[q],
                                   ln_h_g, ln_h_b, ln_c_g, ln_c_b);
        k_fcr<<<GRID_FCR, 256>>>(S->h3[q], S->c3[q], S->h2[q], S->c3[p],
            w_ih2, b_ih2, w_hh1, w_hh2, b_hh1, b_hh2,
            fc_b, fc_w, embed_w, totoken_w, out, t, (t < Tlen - 1) ? 1 : 0, 1);
    }
}

// round 17
// speedup vs baseline: 1.4128x; 1.4128x over previous
#include <cuda_runtime.h>
#include <cuda_bf16.h>
#include <cstdint>
#include <cstddef>

#define Hdim 1024
#define Edim 18432
#define Vdim 32000
#define Tlen 15

// k_fcr grid layout: fcb8 | hh(set0 + merged set1,2) | refine
#define NFC 1000
#define NHH 1024
#define NRF 125
#define GRID_FCR (NFC + NHH + NRF)

struct State {
    float feat[Hdim];
    float h[Hdim], c[Hdim];
    float tmph[Hdim], tmpc[Hdim];
    float h1[Hdim], c1[Hdim];
    float h2[2][Hdim], c2[2][Hdim];
    float h3[2][Hdim], c3[2][Hdim];
    float word[Hdim];
    float hi[Vdim];
    unsigned long long lomax, exmax;
    unsigned ticket1, ticket3, tickF;
};
__device__ State g_s;
__device__ unsigned g_fcw8[(size_t)Vdim * (Hdim / 4)];  // int8-packed fc_w (32.8 MB)
__device__ float g_scale[Vdim];
__device__ float g_sumw[Vdim];
__device__ float g_hhp[3][4 * Hdim];   // hh partials (+bhh) for cells 1..3 of next step

// ---------- helpers ----------
__device__ __forceinline__ float sigf(float x) { return 1.0f / (1.0f + expf(-x)); }

__device__ __forceinline__ float warp_sum(float s) {
#pragma unroll
    for (int o = 16; o; o >>= 1) s += __shfl_xor_sync(0xffffffffu, s, o);
    return s;
}
__device__ __forceinline__ int warp_isum(int s) {
#pragma unroll
    for (int o = 16; o; o >>= 1) s += __shfl_xor_sync(0xffffffffu, s, o);
    return s;
}
__device__ __forceinline__ float warp_max(float s) {
#pragma unroll
    for (int o = 16; o; o >>= 1) s = fmaxf(s, __shfl_xor_sync(0xffffffffu, s, o));
    return s;
}

__device__ __forceinline__ float block_sum(float s) {
    __shared__ float sm[8];
    __shared__ float outv;
    int w = threadIdx.x >> 5, lane = threadIdx.x & 31;
    s = warp_sum(s);
    if (lane == 0) sm[w] = s;
    __syncthreads();
    if (w == 0) {
        float r = (lane < 8) ? sm[lane] : 0.0f;
        r = warp_sum(r);
        if (lane == 0) outv = r;
    }
    __syncthreads();
    float res = outv;
    __syncthreads();
    return res;
}

__device__ __forceinline__ unsigned long long packkey(float v, unsigned idx) {
    unsigned u = __float_as_uint(v);
    u = (u & 0x80000000u) ? ~u : (u | 0x80000000u);
    return ((unsigned long long)u << 32) | (unsigned long long)(0xFFFFFFFFu - idx);
}
__device__ __forceinline__ float key_val(unsigned long long k) {
    unsigned u = (unsigned)(k >> 32);
    u = (u & 0x80000000u) ? (u ^ 0x80000000u) : ~u;
    return __uint_as_float(u);
}
__device__ __forceinline__ int key_idx(unsigned long long k) {
    return (int)(0xFFFFFFFFu - (unsigned)(k & 0xFFFFFFFFull));
}

__device__ __forceinline__ int clamp127(int q) {
    return q < -127 ? -127 : (q > 127 ? 127 : q);
}
__device__ __forceinline__ unsigned pack4(float4 f, float inv) {
    int a = clamp127(__float2int_rn(f.x * inv));
    int b = clamp127(__float2int_rn(f.y * inv));
    int c = clamp127(__float2int_rn(f.z * inv));
    int d = clamp127(__float2int_rn(f.w * inv));
    return (a & 0xFF) | ((b & 0xFF) << 8) | ((c & 0xFF) << 16) | ((d & 0xFF) << 24);
}

// ---------- LayerNorm by one 256-thread block ----------
__device__ void ln256(const float* __restrict__ x, const float* __restrict__ g,
                      const float* __restrict__ b, const float* __restrict__ base,
                      float* __restrict__ o) {
    float xv[4];
    float s = 0.f;
#pragma unroll
    for (int k = 0; k < 4; k++) { xv[k] = x[threadIdx.x + 256 * k]; s += xv[k]; }
    float m = block_sum(s) * (1.f / Hdim);
    float q = 0.f;
#pragma unroll
    for (int k = 0; k < 4; k++) { float d = xv[k] - m; q += d * d; }
    float v = block_sum(q) * (1.f / Hdim);
    float inv = rsqrtf(v + 1e-5f);
#pragma unroll
    for (int k = 0; k < 4; k++) {
        int i = threadIdx.x + 256 * k;
        float r = (xv[k] - m) * inv * g[i] + b[i];
        if (base) r += base[i];
        o[i] = r;
    }
}

// ---------- prologue: fc1 rows (blocks < Hdim) + int8 quantize fc_w (rest) ----------
__global__ void __launch_bounds__(256) k_pro1(
    const float* __restrict__ feats, const float* __restrict__ w,
    const float* __restrict__ bias, const float* __restrict__ fcw32) {
    int wid = threadIdx.x >> 5, lane = threadIdx.x & 31;
    if (blockIdx.x < Hdim) {
        int j = blockIdx.x;
        const float4* Wr = (const float4*)(w + (size_t)j * Edim);
        const float4* X  = (const float4*)feats;
        float s = 0.f;
        for (int i = threadIdx.x; i < Edim / 4; i += 256) {
            float4 a = __ldcs(&Wr[i]), v = X[i];
            s += a.x * v.x + a.y * v.y + a.z * v.z + a.w * v.w;
        }
        s = block_sum(s);
        if (threadIdx.x == 0) g_s.feat[j] = fmaxf(s + bias[j], 0.f);
    } else {
        int r = (blockIdx.x - Hdim) * 8 + wid;
        const float4* Wr = (const float4*)(fcw32 + (size_t)r * Hdim);
        float4 v[8];
        float ma = 0.f, sa = 0.f;
#pragma unroll
        for (int k = 0; k < 8; k++) {
            v[k] = __ldcs(&Wr[lane + 32 * k]);
            ma = fmaxf(ma, fmaxf(fmaxf(fabsf(v[k].x), fabsf(v[k].y)),
                                 fmaxf(fabsf(v[k].z), fabsf(v[k].w))));
            sa += fabsf(v[k].x) + fabsf(v[k].y) + fabsf(v[k].z) + fabsf(v[k].w);
        }
        ma = warp_max(ma);
        sa = warp_sum(sa);
        float mg = fmaxf(ma, 1e-30f);
        float s = mg * (1.f / 127.f);
        float inv = 127.f / mg;
        unsigned* W8 = g_fcw8 + (size_t)r * (Hdim / 4);
#pragma unroll
        for (int k = 0; k < 8; k++) W8[lane + 32 * k] = pack4(v[k], inv);
        if (lane == 0) { g_scale[r] = s; g_sumw[r] = sa; }
    }
}

// ---------- init h/c GEMVs + (last block) prologue LayerNorms ----------
__global__ void __launch_bounds__(256) k_init2(
    const float* __restrict__ wh, const float* __restrict__ bh,
    const float* __restrict__ wc, const float* __restrict__ bc,
    const float* __restrict__ lnhg, const float* __restrict__ lnhb,
    const float* __restrict__ lncg, const float* __restrict__ lncb) {
    int j = blockIdx.x;
    bool ish = j < Hdim;
    int r = ish ? j : j - Hdim;
    const float4* Wr = (const float4*)((ish ? wh : wc) + (size_t)r * Hdim);
    const float4* X  = (const float4*)g_s.feat;
    float4 a = __ldcs(&Wr[threadIdx.x]), v = X[threadIdx.x];
    float s = a.x * v.x + a.y * v.y + a.z * v.z + a.w * v.w;
    s = block_sum(s);
    __shared__ bool lastb;
    if (threadIdx.x == 0) {
        float val = fmaxf(s + (ish ? bh[r] : bc[r]), 0.f);
        if (ish) g_s.tmph[r] = val; else g_s.tmpc[r] = val;
        __threadfence();
        lastb = (atomicAdd(&g_s.ticket1, 1u) == 2u * Hdim - 1u);
    }
    __syncthreads();
    if (!lastb) return;
    ln256(g_s.tmph, lnhg, lnhb, nullptr, g_s.h);
    ln256(g_s.tmpc, lncg, lncb, nullptr, g_s.c);
    if (threadIdx.x == 0) g_s.ticket1 = 0;
}

// ---------- full LSTM cell (step 0 only; R7/R12-proven) ----------
template <bool FUSELN>
__global__ void __launch_bounds__(256) k_cell(
    const float* __restrict__ x, const float* __restrict__ hin, const float* __restrict__ cin,
    const float* __restrict__ wih, const float* __restrict__ whh,
    const float* __restrict__ bih, const float* __restrict__ bhh,
    float* __restrict__ hout, float* __restrict__ cout,
    const float* __restrict__ lnhg, const float* __restrict__ lnhb,
    const float* __restrict__ lncg, const float* __restrict__ lncb) {
    if (FUSELN && blockIdx.x >= Hdim) {
        bool ish = (blockIdx.x == Hdim);
        ln256(ish ? g_s.h1 : g_s.c1,
              ish ? lnhg : lncg, ish ? lnhb : lncb,
              ish ? g_s.h : g_s.c,
              ish ? g_s.tmph : g_s.tmpc);
        return;
    }
    int j = blockIdx.x;
    int w = threadIdx.x >> 5, lane = threadIdx.x & 31;
    const float* Wm  = (w < 4) ? wih : whh;
    const float* vec = (w < 4) ? x : hin;
    int row = j + (w & 3) * Hdim;
    const float4* Wr = (const float4*)(Wm + (size_t)row * Hdim);
    const float4* v4 = (const float4*)vec;
    float s = 0.f;
#pragma unroll
    for (int i = 0; i < 8; i++) {
        float4 a = Wr[lane + 32 * i];
        float4 b = v4[lane + 32 * i];
        s += a.x * b.x + a.y * b.y + a.z * b.z + a.w * b.w;
    }
    s = warp_sum(s);
    __shared__ float red[8];
    if (lane == 0) red[w] = s;
    __syncthreads();
    if (threadIdx.x == 0) {
        float gi = red[0] + red[4] + bih[j]            + bhh[j];
        float gf = red[1] + red[5] + bih[j + Hdim]     + bhh[j + Hdim];
        float gg = red[2] + red[6] + bih[j + 2 * Hdim] + bhh[j + 2 * Hdim];
        float go = red[3] + red[7] + bih[j + 3 * Hdim] + bhh[j + 3 * Hdim];
        float cn = sigf(gf) * cin[j] + sigf(gi) * tanhf(gg);
        cout[j] = cn;
        hout[j] = sigf(go) * tanhf(cn);
    }
}

// ---------- hh-half GEMV body: g_hhp[set][g*H+j] = Whh[g*H+j,:]@hin + bhh ----------
__device__ __forceinline__ void hh_body(int set, int b, const float* __restrict__ hin,
                                        const float* __restrict__ W,
                                        const float* __restrict__ bb) {
    int w = threadIdx.x >> 5, lane = threadIdx.x & 31;
    int g = w & 3, rl = w >> 2;
    int row = g * Hdim + b * 2 + rl;
    const float4* Wr = (const float4*)(W + (size_t)row * Hdim);
    const float4* v4 = (const float4*)hin;
    float s = 0.f;
#pragma unroll
    for (int i = 0; i < 8; i++) {
        float4 a = Wr[lane + 32 * i];
        float4 vb = v4[lane + 32 * i];
        s += a.x * vb.x + a.y * vb.y + a.z * vb.z + a.w * vb.w;
    }
    s = warp_sum(s);
    if (lane == 0) g_hhp[set][row] = s + bb[row];
}

// ---------- combine: ih-half GEMV + hh partial + pointwise (R12 shape) ----------
template <bool FUSELN>
__global__ void __launch_bounds__(256) k_comb(
    const float* __restrict__ x, const float* __restrict__ cin, int set,
    const float* __restrict__ wih, const float* __restrict__ bih,
    float* __restrict__ hout, float* __restrict__ cout,
    const float* __restrict__ lnhg, const float* __restrict__ lnhb,
    const float* __restrict__ lncg, const float* __restrict__ lncb) {
    if (FUSELN && blockIdx.x >= 512) {
        bool ish = (blockIdx.x == 512);
        ln256(ish ? g_s.h1 : g_s.c1,
              ish ? lnhg : lncg, ish ? lnhb : lncb,
              ish ? g_s.h : g_s.c,
              ish ? g_s.tmph : g_s.tmpc);
        return;
    }
    int tid = threadIdx.x;
    int w = tid >> 5, lane = tid & 31;
    int g = w & 3, rl = w >> 2;
    int j = blockIdx.x * 2 + rl;
    int row = g * Hdim + j;
    const float4* Wr = (const float4*)(wih + (size_t)row * Hdim);
    const float4* v4 = (const float4*)x;
    float s = 0.f;
#pragma unroll
    for (int i = 0; i < 8; i++) {
        float4 a = Wr[lane + 32 * i];
        float4 vb = v4[lane + 32 * i];
        s += a.x * vb.x + a.y * vb.y + a.z * vb.z + a.w * vb.w;
    }
    s = warp_sum(s);
    __shared__ float red[8];
    if (lane == 0) red[w] = s + bih[row] + g_hhp[set][row];
    __syncthreads();
    if (tid == 0 || tid == 128) {
        int rr = tid >> 7;
        int jj = blockIdx.x * 2 + rr;
        float gi = red[rr * 4 + 0], gf = red[rr * 4 + 1];
        float gg = red[rr * 4 + 2], go = red[rr * 4 + 3];
        float cn = sigf(gf) * cin[jj] + sigf(gi) * tanhf(gg);
        cout[jj] = cn;
        hout[jj] = sigf(go) * tanhf(cn);
    }
}

// ---------- mega-kernel: fcb8 + next-step hh (set0 + merged 1,2) + refine ----------
__global__ void __launch_bounds__(256) k_fcr(
    const float* __restrict__ x,       // = h3 current
    const float* __restrict__ h2cur,
    const float* __restrict__ w_hh1, const float* __restrict__ w_hh2,
    const float* __restrict__ b_hh1, const float* __restrict__ b_hh2,
    const float* __restrict__ fcb, const float* __restrict__ fcw32,
    const float* __restrict__ embed, const float* __restrict__ tot,
    float* __restrict__ out, int t, int do_hh) {
    int bid = blockIdx.x;
    int tid = threadIdx.x, wid = tid >> 5, lane = tid & 31;
    const float4* X = (const float4*)x;

    if (bid < NFC) {   // ---- fcb8 ----
        float4 xv[8];
        float ma = 0.f, sa = 0.f;
#pragma unroll
        for (int k = 0; k < 8; k++) {
            xv[k] = X[lane + 32 * k];
            ma = fmaxf(ma, fmaxf(fmaxf(fabsf(xv[k].x), fabsf(xv[k].y)),
                                 fmaxf(fabsf(xv[k].z), fabsf(xv[k].w))));
            sa += fabsf(xv[k].x) + fabsf(xv[k].y) + fabsf(xv[k].z) + fabsf(xv[k].w);
        }
        ma = warp_max(ma);
        float sumAbsX = warp_sum(sa);
        float mg = fmaxf(ma, 1e-30f);
        float sx = mg * (1.f / 127.f);
        float invx = 127.f / mg;
        unsigned qx[8];
#pragma unroll
        for (int k = 0; k < 8; k++) qx[k] = pack4(xv[k], invx);
        unsigned long long wbest = 0ull;
        int r0 = (bid * 8 + wid) * 4;
#pragma unroll
        for (int rr = 0; rr < 4; rr++) {
            int r = r0 + rr;
            const unsigned* W8 = g_fcw8 + (size_t)r * (Hdim / 4);
            int acc = 0;
#pragma unroll
            for (int k = 0; k < 8; k++)
                acc = __dp4a((int)W8[lane + 32 * k], (int)qx[k], acc);
            acc = warp_isum(acc);
            if (lane == 0) {
                float sr = g_scale[r];
                float v = sr * sx * (float)acc + fcb[r];
                float err = (0.5f * sx * g_sumw[r] + 0.5f * sr * (sumAbsX + 512.f * sx)) * 1.1f
                            + 1e-7f;
                g_s.hi[r] = v + err;
                unsigned long long key = packkey(v - err, (unsigned)r);
                if (key > wbest) wbest = key;
            }
        }
        __shared__ unsigned long long sb[8];
        if (lane == 0) sb[wid] = wbest;
        __syncthreads();
        if (tid == 0) {
            unsigned long long m = sb[0];
#pragma unroll
            for (int k = 1; k < 8; k++) if (sb[k] > m) m = sb[k];
            atomicMax(&g_s.lomax, m);
            __threadfence();
            atomicAdd(&g_s.tickF, 1u);
        }
        return;
    }

    if (bid < NFC + NHH) {   // ---- hh for next step ----
        if (do_hh) {
            int local = bid - NFC;
            if (local < 512) {   // set0: Whh1 @ tmph
                hh_body(0, local, g_s.tmph, w_hh1, b_hh1);
            } else {             // merged sets 1,2: one w_hh2 pass, dot vs h2 and h3
                int b = local - 512;
                int g = wid & 3, rl = wid >> 2;
                int row = g * Hdim + b * 2 + rl;
                const float4* Wr = (const float4*)(w_hh2 + (size_t)row * Hdim);
                const float4* A = (const float4*)h2cur;
                float s1 = 0.f, s2 = 0.f;
#pragma unroll
                for (int i = 0; i < 8; i++) {
                    float4 a  = Wr[lane + 32 * i];
                    float4 va = A[lane + 32 * i];
                    float4 vb = X[lane + 32 * i];
                    s1 += a.x * va.x + a.y * va.y + a.z * va.z + a.w * va.w;
                    s2 += a.x * vb.x + a.y * vb.y + a.z * vb.z + a.w * vb.w;
                }
                s1 = warp_sum(s1);
                s2 = warp_sum(s2);
                if (lane == 0) {
                    float bb = b_hh2[row];
                    g_hhp[1][row] = s1 + bb;
                    g_hhp[2][row] = s2 + bb;
                }
            }
        }
        return;
    }

    // ---- refine (NRF blocks; spin until all fcb8 blocks done) ----
    if (tid == 0) {
        volatile unsigned* vc = &g_s.tickF;
        while (*vc < (unsigned)NFC) __nanosleep(64);
    }
    __syncthreads();
    int rb = bid - (NFC + NHH);
    __shared__ int cand[256];
    __shared__ int cnt;
    __shared__ unsigned long long swr[8];
    __shared__ bool lastb;
    __shared__ int s_idx;
    __shared__ float s_tok;
    if (tid == 0) cnt = 0;
    __syncthreads();
    float lo = key_val(g_s.lomax);
    int r = rb * 256 + tid;
    if (__ldcg(&g_s.hi[r]) >= lo) cand[atomicAdd(&cnt, 1)] = r;
    __syncthreads();
    float4 x4c[8];
#pragma unroll
    for (int k = 0; k < 8; k++) x4c[k] = X[lane + 32 * k];
    unsigned long long rbest = 0ull;
    int n = cnt;
    for (int ci = wid; ci < n; ci += 8) {
        int row = cand[ci];
        const float4* Wr = (const float4*)(fcw32 + (size_t)row * Hdim);
        float d = 0.f;
#pragma unroll
        for (int k = 0; k < 8; k++) {
            float4 a = Wr[lane + 32 * k];
            d += a.x * x4c[k].x + a.y * x4c[k].y + a.z * x4c[k].z + a.w * x4c[k].w;
        }
        d = warp_sum(d);
        if (lane == 0) {
            unsigned long long key = packkey(d + fcb[row], (unsigned)row);
            if (key > rbest) rbest = key;
        }
    }
    if (lane == 0) swr[wid] = rbest;
    __syncthreads();
    if (tid == 0) {
        unsigned long long m = swr[0];
#pragma unroll
        for (int k = 1; k < 8; k++) if (swr[k] > m) m = swr[k];
        if (m) atomicMax(&g_s.exmax, m);
        __threadfence();
        lastb = (atomicAdd(&g_s.ticket3, 1u) == NRF - 1u);
    }
    __syncthreads();
    if (!lastb) return;

    if (tid == 0) {
        unsigned long long m = atomicAdd(&g_s.exmax, 0ull);
        s_idx = key_idx(m);
        s_tok = tot[s_idx];
        g_s.lomax = 0ull;
        g_s.exmax = 0ull;
        g_s.ticket3 = 0u;
        g_s.tickF = 0u;
    }
    __syncthreads();
    int idx = s_idx;
    ((float4*)g_s.word)[tid] = ((const float4*)(embed + (size_t)idx * Hdim))[tid];
    out[tid * Tlen + t] = s_tok;   // batch == 256 == blockDim
}

extern "C" void kernel_launch(void* const* d_in, const int* in_sizes, int n_in,
                              void* d_out, int out_size) {
    const float* features  = (const float*)d_in[0];
    const float* fc1_w     = (const float*)d_in[1];
    const float* fc1_b     = (const float*)d_in[2];
    const float* init_h_w  = (const float*)d_in[3];
    const float* init_h_b  = (const float*)d_in[4];
    const float* init_c_w  = (const float*)d_in[5];
    const float* init_c_b  = (const float*)d_in[6];
    const float* ln_h_g    = (const float*)d_in[7];
    const float* ln_h_b    = (const float*)d_in[8];
    const float* ln_c_g    = (const float*)d_in[9];
    const float* ln_c_b    = (const float*)d_in[10];
    const float* w_ih1     = (const float*)d_in[11];
    const float* w_hh1     = (const float*)d_in[12];
    const float* b_ih1     = (const float*)d_in[13];
    const float* b_hh1     = (const float*)d_in[14];
    const float* w_ih2     = (const float*)d_in[15];
    const float* w_hh2     = (const float*)d_in[16];
    const float* b_ih2     = (const float*)d_in[17];
    const float* b_hh2     = (const float*)d_in[18];
    const float* fc_w      = (const float*)d_in[19];
    const float* fc_b      = (const float*)d_in[20];
    const float* embed_w   = (const float*)d_in[21];
    const float* totoken_w = (const float*)d_in[22];
    float* out = (float*)d_out;

    State* S = nullptr;
    cudaGetSymbolAddress((void**)&S, g_s);
    const float* FN = nullptr;

    // prologue
    k_pro1<<<Hdim + Vdim / 8, 256>>>(features, fc1_w, fc1_b, fc_w);
    k_init2<<<2 * Hdim, 256>>>(init_h_w, init_h_b, init_c_w, init_c_b,
                               ln_h_g, ln_h_b, ln_c_g, ln_c_b);

    // ---- step 0: full cells (R12 path) then fcr (with hh for step 1) ----
    k_cell<false><<<Hdim, 256>>>(S->feat, S->h, S->c,
        w_ih1, w_hh1, b_ih1, b_hh1, S->h1, S->c1, FN, FN, FN, FN);
    k_cell<true><<<Hdim + 2, 256>>>(S->h1, S->h, S->c,
        w_ih2, w_hh2, b_ih2, b_hh2, S->h2[0], S->c2[0],
        ln_h_g, ln_h_b, ln_c_g, ln_c_b);
    k_cell<false><<<Hdim, 256>>>(S->h2[0], S->h, S->c,
        w_ih2, w_hh2, b_ih2, b_hh2, S->h3[0], S->c3[0], FN, FN, FN, FN);
    k_fcr<<<GRID_FCR, 256>>>(S->h3[0], S->h2[0],
        w_hh1, w_hh2, b_hh1, b_hh2,
        fc_b, fc_w, embed_w, totoken_w, out, 0, 1);

    // ---- steps 1..14: slim ih-combine chain + fused hh in fcr (R12 structure) ----
    for (int t = 1; t < Tlen; t++) {
        int q = t & 1, p = q ^ 1;
        k_comb<false><<<512, 256>>>(S->word, S->tmpc, 0, w_ih1, b_ih1,
                                    S->h1, S->c1, FN, FN, FN, FN);
        k_comb<true><<<514, 256>>>(S->h1, S->c2[p], 1, w_ih2, b_ih2,
                                   S->h2[q], S->c2[q],
                                   ln_h_g, ln_h_b, ln_c_g, ln_c_b);
        k_comb<false><<<512, 256>>>(S->h2[q], S->c3[p], 2, w_ih2, b_ih2,
                                    S->h3[q], S->c3[q], FN, FN, FN, FN);
        k_fcr<<<GRID_FCR, 256>>>(S->h3[q], S->h2[q],
            w_hh1, w_hh2, b_hh1, b_hh2,
            fc_b, fc_w, embed_w, totoken_w, out, t, (t < Tlen - 1) ? 1 : 0);
    }
}